// round 9
// baseline (speedup 1.0000x reference)
#include <cuda_runtime.h>

typedef unsigned long long ULL;

#define B_DIM 16
#define C_DIM 64
#define K_DIM 207
#define L_DIM 64
#define KL (K_DIM*L_DIM)      /* 13248 */
#define KK (K_DIM*K_DIM)      /* 42849 */
#define CIN 320

// scratch (allocation-free rule: __device__ globals)
__device__ float g_S[2*B_DIM*KK];                       // A0^2, A1^2 per batch (~5.5MB)
__device__ float g_t[(size_t)4*B_DIM*C_DIM*KL];         // A0x, S0x, A1x, S1x (~217MB)

// ---------------- f32x2 helpers (FFMA2 path, sm_100+) ----------------
__device__ __forceinline__ ULL pack2(float v) {
    ULL r; asm("mov.b64 %0, {%1, %1};" : "=l"(r) : "r"(__float_as_uint(v)));
    return r;
}
__device__ __forceinline__ ULL packxy(float a, float b) {
    ULL r; asm("mov.b64 %0, {%1, %2};" : "=l"(r) : "r"(__float_as_uint(a)), "r"(__float_as_uint(b)));
    return r;
}
__device__ __forceinline__ ULL fma2(ULL a, ULL b, ULL c) {
    ULL d; asm("fma.rn.f32x2 %0, %1, %2, %3;" : "=l"(d) : "l"(a), "l"(b), "l"(c));
    return d;
}
__device__ __forceinline__ float2 unpack2(ULL v) {
    unsigned lo, hi;
    asm("mov.b64 {%0, %1}, %2;" : "=r"(lo), "=r"(hi) : "l"(v));
    return make_float2(__uint_as_float(lo), __uint_as_float(hi));
}

// ================= kernel 1: S = A @ A per (s, b) =================
// grid (52, 16, 2): blockIdx.x = jt*4 + pt, y = b, z = s.  256 threads.
// output tile 16j x 64p, thread = 1j x 4p.
__global__ __launch_bounds__(256) void square_kernel(
    const float* __restrict__ a0, const float* __restrict__ a1)
{
    __shared__ float As[16][16];
    __shared__ float Bs[16][64];
    const int tid = threadIdx.x;
    const int jt = blockIdx.x >> 2, pt = blockIdx.x & 3;
    const int b = blockIdx.y, s = blockIdx.z;
    const float* A = (s == 0 ? a0 : a1) + (size_t)b*KK;
    float* S = g_S + (size_t)(s*B_DIM + b)*KK;

    const int jl = tid >> 4, pg = tid & 15;
    const int j = jt*16 + jl;
    const int p0 = pt*64 + pg*4;

    float acc0 = 0.f, acc1 = 0.f, acc2 = 0.f, acc3 = 0.f;
    for (int kt = 0; kt < 13; ++kt) {
        const int kb = kt*16;
        {
            int rr = tid >> 4, cc = tid & 15;
            int jj = jt*16 + rr, kk = kb + cc;
            As[rr][cc] = (jj < K_DIM && kk < K_DIM) ? A[(size_t)jj*K_DIM + kk] : 0.f;
        }
        #pragma unroll
        for (int q = 0; q < 4; ++q) {
            int idx = tid + q*256;
            int rr = idx >> 6, cc = idx & 63;
            int kk = kb + rr, pp = pt*64 + cc;
            Bs[rr][cc] = (kk < K_DIM && pp < K_DIM) ? A[(size_t)kk*K_DIM + pp] : 0.f;
        }
        __syncthreads();
        #pragma unroll
        for (int k = 0; k < 16; ++k) {
            float a = As[jl][k];
            float4 bv = *(const float4*)&Bs[k][pg*4];
            acc0 += a*bv.x; acc1 += a*bv.y; acc2 += a*bv.z; acc3 += a*bv.w;
        }
        __syncthreads();
    }
    if (j < K_DIM) {
        float* Sp = S + (size_t)j*K_DIM + p0;
        if (p0 + 3 < K_DIM) { Sp[0]=acc0; Sp[1]=acc1; Sp[2]=acc2; Sp[3]=acc3; }
        else {
            if (p0     < K_DIM) Sp[0] = acc0;
            if (p0 + 1 < K_DIM) Sp[1] = acc1;
            if (p0 + 2 < K_DIM) Sp[2] = acc2;
        }
    }
}

// ================= kernel 2: diffuse  t_m[b,c,j,l] = sum_k M_m[j,k] x[b,c,k,l] =================
// grid (7 jt, 4 m, 16 b), 256 threads, 1 CTA/SM (136KB smem).
// smem: Msm transposed [207 k][36 pad] (j-tile 32), Xsm [2 c][207 k][64 l].
// thread tile: 8j (as 4 j-pairs, f32x2) x 2l; 2 c-groups of 128 threads.
__global__ __launch_bounds__(256, 1) void diffuse_kernel(
    const float* __restrict__ x, const float* __restrict__ a0,
    const float* __restrict__ a1)
{
    extern __shared__ float sm[];
    float* Msm = sm;                 // [207][36]
    float* Xsm = sm + K_DIM*36;      // [2][KL]
    const int tid = threadIdx.x;
    const int jt = blockIdx.x, m = blockIdx.y, b = blockIdx.z;
    const int j0 = jt * 32;

    const float* M =
        (m == 0) ? a0  + (size_t)b*KK :
        (m == 1) ? g_S + (size_t)b*KK :
        (m == 2) ? a1  + (size_t)b*KK :
                   g_S + (size_t)(B_DIM + b)*KK;

    // load M tile transposed: Msm[k][jl] = M[j0+jl][k], zero-fill out-of-range rows
    for (int e = tid; e < K_DIM*32; e += 256) {
        int jl = e / K_DIM;
        int k  = e - jl*K_DIM;
        int j  = j0 + jl;
        Msm[k*36 + jl] = (j < K_DIM) ? M[(size_t)j*K_DIM + k] : 0.f;
    }

    const int cg = tid >> 7;
    const int t  = tid & 127;
    const int lg = t & 31, jg = t >> 5;
    const int l0 = lg*2, jb = jg*8;

    const float* xb = x + (size_t)b*C_DIM*KL;
    float* tb = g_t + ((size_t)(m*B_DIM + b))*C_DIM*KL;

    for (int c2 = 0; c2 < 32; ++c2) {
        __syncthreads();
        const float4* src = (const float4*)(xb + (size_t)(2*c2)*KL);
        float4* dst = (float4*)Xsm;
        for (int v = tid; v < (2*KL)/4; v += 256) dst[v] = src[v];
        __syncthreads();

        ULL acc[4][2] = {};
        const float* Xc = Xsm + cg*KL + l0;
        const float* Mc = Msm + jb;
        #pragma unroll 3
        for (int k = 0; k < K_DIM; ++k) {
            ulonglong2 p0 = *(const ulonglong2*)(Mc + k*36);
            ulonglong2 p1 = *(const ulonglong2*)(Mc + k*36 + 4);
            float2 xv = *(const float2*)(Xc + k*64);
            ULL xa = pack2(xv.x), xb2 = pack2(xv.y);
            ULL mj[4] = {p0.x, p0.y, p1.x, p1.y};
            #pragma unroll
            for (int q = 0; q < 4; ++q) {
                acc[q][0] = fma2(mj[q], xa,  acc[q][0]);
                acc[q][1] = fma2(mj[q], xb2, acc[q][1]);
            }
        }

        const int c = 2*c2 + cg;
        float* out = tb + (size_t)c*KL + l0;
        #pragma unroll
        for (int q = 0; q < 4; ++q) {
            int j = j0 + jb + 2*q;
            float2 v0 = unpack2(acc[q][0]);   // (j, j+1) at column l0
            float2 v1 = unpack2(acc[q][1]);   // (j, j+1) at column l0+1
            if (j     < K_DIM) *(float2*)(out + (size_t)j*64)     = make_float2(v0.x, v1.x);
            if (j + 1 < K_DIM) *(float2*)(out + (size_t)(j+1)*64) = make_float2(v0.y, v1.y);
        }
    }
}

// ================= kernel 3: conv  y[b,o,kl] = sum_i W[o,i] H[b,i,kl] + bias[o] =================
// H channel blocks: [x | g_t m=0 | m=1 | m=2 | m=3].
// grid (207 kl-tiles of 64, 16 b), 256 threads, 2 CTAs/SM (103KB smem).
// smem: Ws transposed [320 i][68 pad], Hs double-buffered [2][32 i][64 kl].
// thread tile: 8o (4 o-pairs, f32x2) x 2kl.
__global__ __launch_bounds__(256, 2) void conv_kernel(
    const float* __restrict__ x, const float* __restrict__ W,
    const float* __restrict__ bias, float* __restrict__ y)
{
    extern __shared__ float sm[];
    float* Ws = sm;                   // [320][68]
    float* Hs = sm + CIN*68;          // [2][32*64]
    const int tid = threadIdx.x;
    const int b = blockIdx.y;
    const int kl0 = blockIdx.x * 64;

    for (int e = tid; e < CIN*C_DIM; e += 256) {
        int o = e / CIN, i = e - o*CIN;
        Ws[i*68 + o] = W[e];          // W is [o][i] row-major; read coalesced over i
    }

    const int lg = tid & 31, og = tid >> 5;
    const int kll = lg*2, o0 = og*8;

    ULL acc[4][2];
    #pragma unroll
    for (int q = 0; q < 4; ++q) {
        float2 bb = *(const float2*)&bias[o0 + 2*q];
        ULL bp = packxy(bb.x, bb.y);
        acc[q][0] = bp; acc[q][1] = bp;
    }

    const int r  = tid >> 4;          // 0..15
    const int c4 = (tid & 15) * 4;    // 0..60

    // reg-staged double-buffered H chunks of 32 i
    float4 st0, st1;
    {   // prologue: chunk 0 rows are all x (i = 0..31 < 64)
        st0 = *(const float4*)(x + ((size_t)(b*C_DIM + r     ))*KL + kl0 + c4);
        st1 = *(const float4*)(x + ((size_t)(b*C_DIM + 16 + r))*KL + kl0 + c4);
    }
    for (int ch = 0; ch < 10; ++ch) {
        float* Hb = Hs + (ch & 1) * 2048;
        *(float4*)&Hb[r*64 + c4]        = st0;
        *(float4*)&Hb[(16 + r)*64 + c4] = st1;
        __syncthreads();
        if (ch < 9) {
            int ib = (ch + 1) * 32;
            int i0 = ib + r, i1 = ib + 16 + r;
            const float* rp0 = (i0 < 64)
                ? x   + ((size_t)(b*C_DIM + i0))*KL
                : g_t + ((size_t)((((i0 - 64) >> 6)*B_DIM + b)*C_DIM + ((i0 - 64) & 63)))*KL;
            const float* rp1 = (i1 < 64)
                ? x   + ((size_t)(b*C_DIM + i1))*KL
                : g_t + ((size_t)((((i1 - 64) >> 6)*B_DIM + b)*C_DIM + ((i1 - 64) & 63)))*KL;
            st0 = *(const float4*)(rp0 + kl0 + c4);
            st1 = *(const float4*)(rp1 + kl0 + c4);
        }
        const float* Wc = Ws + ch*32*68 + o0;
        const float* Hc = Hb + kll;
        #pragma unroll 4
        for (int ii = 0; ii < 32; ++ii) {
            ulonglong2 w0 = *(const ulonglong2*)(Wc + ii*68);
            ulonglong2 w1 = *(const ulonglong2*)(Wc + ii*68 + 4);
            float2 hv = *(const float2*)(Hc + ii*64);
            ULL ha = pack2(hv.x), hb2 = pack2(hv.y);
            ULL wv[4] = {w0.x, w0.y, w1.x, w1.y};
            #pragma unroll
            for (int q = 0; q < 4; ++q) {
                acc[q][0] = fma2(wv[q], ha,  acc[q][0]);
                acc[q][1] = fma2(wv[q], hb2, acc[q][1]);
            }
        }
        __syncthreads();
    }

    float* yo = y + ((size_t)b*C_DIM)*KL + kl0 + kll;
    #pragma unroll
    for (int q = 0; q < 4; ++q) {
        float2 v0 = unpack2(acc[q][0]);   // (o, o+1) at kll
        float2 v1 = unpack2(acc[q][1]);   // (o, o+1) at kll+1
        int olo = o0 + 2*q;
        *(float2*)(yo + (size_t)olo*KL)     = make_float2(v0.x, v1.x);
        *(float2*)(yo + (size_t)(olo+1)*KL) = make_float2(v0.y, v1.y);
    }
}

// =============================================================================
extern "C" void kernel_launch(void* const* d_in, const int* in_sizes, int n_in,
                              void* d_out, int out_size) {
    const float* x    = (const float*)d_in[0];
    const float* a0   = (const float*)d_in[1];
    const float* a1   = (const float*)d_in[2];
    const float* W    = (const float*)d_in[3];
    const float* bias = (const float*)d_in[4];
    float* y = (float*)d_out;

    const int diffuse_smem = (K_DIM*36 + 2*KL) * 4;          // 135792
    const int conv_smem    = (CIN*68 + 2*32*64) * 4;          // 103424
    cudaFuncSetAttribute(diffuse_kernel, cudaFuncAttributeMaxDynamicSharedMemorySize, diffuse_smem);
    cudaFuncSetAttribute(conv_kernel,    cudaFuncAttributeMaxDynamicSharedMemorySize, conv_smem);

    square_kernel <<<dim3(52, 16, 2), 256>>>(a0, a1);
    diffuse_kernel<<<dim3(7, 4, 16),  256, diffuse_smem>>>(x, a0, a1);
    conv_kernel   <<<dim3(207, 16),   256, conv_smem>>>(x, W, bias, y);
}